// round 9
// baseline (speedup 1.0000x reference)
#include <cuda_runtime.h>
#include <cstdint>

#define B_ 4
#define H_ 16
#define S_ 1024
#define D_ 64

#define KEEP_THRESH 0xE6666600u   // bits < thresh  <=>  uniform < 0.9f (verified)

// ---------------------------------------------------------------------------
// Threefry-2x32 specialized for key (0,42), returns keep bit for counter (0,c).
// Bit-exact vs JAX partitionable path (verified rel_err 6.4e-8 in fp32 kernel).
// ---------------------------------------------------------------------------
__device__ __forceinline__ uint32_t tf_keep(uint32_t ctr) {
    const uint32_t KS2 = 0x1BD11BDAu ^ 42u;
    uint32_t x0 = 0u, x1 = ctr + 42u;
#define TF_R(r) { x0 += x1; x1 = __funnelshift_l(x1, x1, (r)); x1 ^= x0; }
    TF_R(13) TF_R(15) TF_R(26) TF_R(6)
    x0 += 42u;  x1 += KS2 + 1u;
    TF_R(17) TF_R(29) TF_R(16) TF_R(24)
    x0 += KS2;  x1 += 2u;
    TF_R(13) TF_R(15) TF_R(26) TF_R(6)
    /* x0 += 0 */ x1 += 45u;
    TF_R(17) TF_R(29) TF_R(16) TF_R(24)
    x0 += 42u;  x1 += KS2 + 4u;
    TF_R(13) TF_R(15) TF_R(26) TF_R(6)
    x0 += KS2;  x1 += 5u;
#undef TF_R
    return ((x0 ^ x1) < KEEP_THRESH) ? 1u : 0u;
}

// ---------------------------------------------------------------------------
// bf16 helpers
// ---------------------------------------------------------------------------
__device__ __forceinline__ uint32_t pack2(float lo, float hi) {
    uint32_t r;
    asm("cvt.rn.bf16x2.f32 %0, %1, %2;" : "=r"(r) : "f"(hi), "f"(lo));
    return r;
}
__device__ __forceinline__ float blo(uint32_t w) { return __uint_as_float(w << 16); }
__device__ __forceinline__ float bhi(uint32_t w) { return __uint_as_float(w & 0xffff0000u); }
__device__ __forceinline__ void split2(float a, float b, uint32_t& h, uint32_t& l) {
    h = pack2(a, b);
    l = pack2(a - blo(h), b - bhi(h));
}

// d += A(bf16) * B(bf16), m16n8k16
__device__ __forceinline__ void mma16(float d[4], const uint32_t a[4],
                                      uint32_t b0, uint32_t b1) {
    asm volatile(
        "mma.sync.aligned.m16n8k16.row.col.f32.bf16.bf16.f32 "
        "{%0,%1,%2,%3}, {%4,%5,%6,%7}, {%8,%9}, {%0,%1,%2,%3};"
        : "+f"(d[0]), "+f"(d[1]), "+f"(d[2]), "+f"(d[3])
        : "r"(a[0]), "r"(a[1]), "r"(a[2]), "r"(a[3]), "r"(b0), "r"(b1));
}

__device__ __forceinline__ void ldm_x4(uint32_t r[4], uint32_t addr) {
    asm volatile("ldmatrix.sync.aligned.m8n8.x4.shared.b16 {%0,%1,%2,%3}, [%4];"
                 : "=r"(r[0]), "=r"(r[1]), "=r"(r[2]), "=r"(r[3]) : "r"(addr));
}

#define PW 36   // word stride: 144 B/row -> ldmatrix rows land on distinct banks

// word offsets (no aliasing; P lives in registers)
#define W_QH 0
#define W_QL (128 * PW)
#define W_KH (2 * 128 * PW)
#define W_KL (W_KH + 64 * PW)
#define W_VH (W_KL + 64 * PW)
#define W_VL (W_VH + 64 * PW)
#define W_TOT (W_VL + 64 * PW)          // 18432 words = 73728 B -> 2 CTAs/SM

// ---------------------------------------------------------------------------
__global__ void __launch_bounds__(256, 2)
attn_kernel(const float* __restrict__ Q, const float* __restrict__ K,
            const float* __restrict__ V, const uint32_t* __restrict__ scale_ptr,
            float* __restrict__ O) {
    extern __shared__ uint32_t smw[];

    const int tid  = threadIdx.x;
    const int warp = tid >> 5;           // 0..7, owns rows [16w, 16w+16)
    const int lane = tid & 31;
    const int gid  = lane >> 2;          // 0..7
    const int tig  = lane & 3;           // 0..3
    const int bh   = blockIdx.y;
    const int qb   = blockIdx.x << 7;
    const int r0   = warp * 16 + gid;

    uint32_t sw = *scale_ptr;
    float scale = (sw & 0x7f800000u) ? __uint_as_float(sw) : (float)(int)sw;

    // per-lane ldmatrix base addresses (byte, shared space)
    const uint32_t sb = (uint32_t)__cvta_generic_to_shared(smw);
    const uint32_t laneA = (uint32_t)((lane & 15) * PW + ((lane & 16) ? 4 : 0));
    const uint32_t laneBK = (uint32_t)(((lane < 16) ? W_KH : W_KL)
                                       + (lane & 7) * PW + ((lane & 8) ? 4 : 0));
    const uint32_t laneBV = (uint32_t)(((lane < 16) ? W_VH : W_VL)
                                       + (lane & 7) * PW + ((lane & 8) ? 4 : 0));
    const uint32_t aQH = sb + 4u * (W_QH + (uint32_t)(warp * 16) * PW + laneA);
    const uint32_t aQL = sb + 4u * (W_QL + (uint32_t)(warp * 16) * PW + laneA);
    const uint32_t aK  = sb + 4u * laneBK;
    const uint32_t aV  = sb + 4u * laneBV;

    // global bit-index base for this lane's dropout rows (row r0 and r0+8)
    const uint32_t bit_base =
        ((uint32_t)(bh * S_ + qb + r0) << 10) + 2u * (uint32_t)tig;

    // ---- Q prologue: stage scaled hi/lo bf16x2 words into smem ----
    {
        int r = tid >> 1, half = (tid & 1) * 32;
        const float4* Qp = reinterpret_cast<const float4*>(
            Q + ((size_t)bh * S_ + qb + r) * D_ + half);
        int wb = r * PW + (half >> 1);
#pragma unroll
        for (int i = 0; i < 8; i++) {
            float4 v = Qp[i];
            uint32_t h0, l0, h1, l1;
            split2(v.x * scale, v.y * scale, h0, l0);
            split2(v.z * scale, v.w * scale, h1, l1);
            smw[W_QH + wb + 2 * i]     = h0;
            smw[W_QH + wb + 2 * i + 1] = h1;
            smw[W_QL + wb + 2 * i]     = l0;
            smw[W_QL + wb + 2 * i + 1] = l1;
        }
    }

    float m_[2], l_[2];
    float o[8][4];
    m_[0] = m_[1] = -1e30f;
    l_[0] = l_[1] = 0.f;
#pragma unroll
    for (int n = 0; n < 8; n++)
#pragma unroll
        for (int c = 0; c < 4; c++) o[n][c] = 0.f;

    __syncthreads();

#pragma unroll 1
    for (int t = 0; t < 16; t++) {
        if (t) __syncthreads();          // prev-iter K/V readers done

        // ---- K tile: thread owns 16 d-elems of one key row; split hi/lo ----
        {
            int r = tid >> 2, qv = (tid & 3) << 4;
            const float4* Kt = reinterpret_cast<const float4*>(
                K + ((size_t)bh * S_ + t * 64 + r) * D_ + qv);
            uint32_t kh[8], kl[8];
#pragma unroll
            for (int i = 0; i < 4; i++) {
                float4 v = Kt[i];
                split2(v.x, v.y, kh[2 * i],     kl[2 * i]);
                split2(v.z, v.w, kh[2 * i + 1], kl[2 * i + 1]);
            }
            int wb = r * PW + (qv >> 1);
            *reinterpret_cast<uint4*>(smw + W_KH + wb) =
                make_uint4(kh[0], kh[1], kh[2], kh[3]);
            *reinterpret_cast<uint4*>(smw + W_KH + wb + 4) =
                make_uint4(kh[4], kh[5], kh[6], kh[7]);
            *reinterpret_cast<uint4*>(smw + W_KL + wb) =
                make_uint4(kl[0], kl[1], kl[2], kl[3]);
            *reinterpret_cast<uint4*>(smw + W_KL + wb + 4) =
                make_uint4(kl[4], kl[5], kl[6], kl[7]);
        }

        // ---- V tile: transposed [d][key-pair word], split hi/lo ----
        {
            int kp = tid & 31, db = (tid >> 5) << 3;
            const float* Vb = V + ((size_t)bh * S_ + t * 64 + 2 * kp) * D_ + db;
            float4 a0 = reinterpret_cast<const float4*>(Vb)[0];
            float4 a1 = reinterpret_cast<const float4*>(Vb)[1];
            float4 b0 = reinterpret_cast<const float4*>(Vb + D_)[0];
            float4 b1 = reinterpret_cast<const float4*>(Vb + D_)[1];
            float fa[8] = {a0.x, a0.y, a0.z, a0.w, a1.x, a1.y, a1.z, a1.w};
            float fb[8] = {b0.x, b0.y, b0.z, b0.w, b1.x, b1.y, b1.z, b1.w};
#pragma unroll
            for (int i = 0; i < 8; i++) {
                uint32_t h, l;
                split2(fa[i], fb[i], h, l);    // lo=key 2kp, hi=key 2kp+1
                smw[W_VH + (db + i) * PW + kp] = h;
                smw[W_VL + (db + i) * PW + kp] = l;
            }
        }
        __syncthreads();

        // ---- QK: 3-term bf16, Q via ldmatrix, K via ldmatrix.x4 ----
        float s[8][4];
#pragma unroll
        for (int n = 0; n < 8; n++)
#pragma unroll
            for (int c = 0; c < 4; c++) s[n][c] = 0.f;

#pragma unroll
        for (int ks = 0; ks < 4; ks++) {
            uint32_t qh[4], ql[4];
            ldm_x4(qh, aQH + ks * 32u);
            ldm_x4(ql, aQL + ks * 32u);
#pragma unroll
            for (int n = 0; n < 8; n++) {
                uint32_t kb[4];
                ldm_x4(kb, aK + 4u * (uint32_t)(n * 8 * PW + ks * 8));
                mma16(s[n], qh, kb[0], kb[1]);
                mma16(s[n], ql, kb[0], kb[1]);
                mma16(s[n], qh, kb[2], kb[3]);
            }
        }

        // ---- fused dropout mask: 32 threefry evals (fills HMMA latency) ----
        // lane bit (2n+e) of lm_h = keep for (row r0+8h, col 8n+2tig+e)
        uint32_t lm0 = 0u, lm1 = 0u;
        {
            uint32_t c0 = bit_base + (uint32_t)(t * 64);
            uint32_t c1 = c0 + (8u << 10);
#pragma unroll 1
            for (int j = 0; j < 8; j++) {
                uint32_t cj0 = c0 + 8u * (uint32_t)j;
                uint32_t cj1 = c1 + 8u * (uint32_t)j;
                lm0 |= tf_keep(cj0)      << (2 * j);
                lm0 |= tf_keep(cj0 + 1u) << (2 * j + 1);
                lm1 |= tf_keep(cj1)      << (2 * j);
                lm1 |= tf_keep(cj1 + 1u) << (2 * j + 1);
            }
        }

        // ---- online softmax (row lives on a lane quad) ----
#pragma unroll
        for (int h = 0; h < 2; h++) {
            float mx = -1e30f;
#pragma unroll
            for (int n = 0; n < 8; n++)
                mx = fmaxf(mx, fmaxf(s[n][2 * h], s[n][2 * h + 1]));
            mx = fmaxf(mx, __shfl_xor_sync(0xffffffffu, mx, 1));
            mx = fmaxf(mx, __shfl_xor_sync(0xffffffffu, mx, 2));
            float mnew = fmaxf(m_[h], mx);
            float corr = __expf(m_[h] - mnew);
            m_[h] = mnew;
            float sum = 0.f;
#pragma unroll
            for (int n = 0; n < 8; n++) {
                float e0 = __expf(s[n][2 * h] - mnew);
                float e1 = __expf(s[n][2 * h + 1] - mnew);
                s[n][2 * h] = e0;
                s[n][2 * h + 1] = e1;
                sum += e0 + e1;
            }
            sum += __shfl_xor_sync(0xffffffffu, sum, 1);
            sum += __shfl_xor_sync(0xffffffffu, sum, 2);
            l_[h] = l_[h] * corr + sum;
#pragma unroll
            for (int n = 0; n < 8; n++) {
                o[n][2 * h] *= corr;
                o[n][2 * h + 1] *= corr;
            }
        }

        // ---- PV: dropout + pack P chunk in regs, V via ldmatrix.x4 ----
#pragma unroll
        for (int ks = 0; ks < 4; ks++) {
            uint32_t aph[4], apl[4];
#pragma unroll
            for (int q = 0; q < 4; q++) {          // q = 2*(n-2ks) + h
                int n = 2 * ks + (q >> 1);
                int h = q & 1;
                uint32_t lm = h ? lm1 : lm0;
                float p0 = ((lm >> (2 * n)) & 1u)     ? s[n][2 * h] : 0.f;
                float p1 = ((lm >> (2 * n + 1)) & 1u) ? s[n][2 * h + 1] : 0.f;
                int ar = (q >> 1) * 2 + h;         // n-low: a0/a1, n-high: a2/a3
                split2(p0, p1, aph[ar], apl[ar]);
            }
#pragma unroll
            for (int n = 0; n < 8; n++) {
                uint32_t vb[4];
                ldm_x4(vb, aV + 4u * (uint32_t)(n * 8 * PW + ks * 8));
                mma16(o[n], aph, vb[0], vb[1]);
                mma16(o[n], aph, vb[2], vb[3]);
                mma16(o[n], apl, vb[0], vb[1]);
            }
        }
    }

    // ---- epilogue: O / (0.9 * l), write global ----
#pragma unroll
    for (int h = 0; h < 2; h++) {
        float inv = 1.f / (0.9f * l_[h]);
        int row = qb + r0 + h * 8;
        float* Op = O + ((size_t)bh * S_ + row) * D_;
#pragma unroll
        for (int n = 0; n < 8; n++) {
            float2 v;
            v.x = o[n][2 * h] * inv;
            v.y = o[n][2 * h + 1] * inv;
            *reinterpret_cast<float2*>(Op + n * 8 + 2 * tig) = v;
        }
    }
}

// ---------------------------------------------------------------------------
extern "C" void kernel_launch(void* const* d_in, const int* in_sizes, int n_in,
                              void* d_out, int out_size) {
    (void)in_sizes; (void)n_in; (void)out_size;
    const float*    Q  = (const float*)d_in[0];
    const float*    K  = (const float*)d_in[1];
    const float*    V  = (const float*)d_in[2];
    const uint32_t* SC = (const uint32_t*)d_in[3];
    float*          O  = (float*)d_out;

    const int smem = W_TOT * (int)sizeof(uint32_t);   // 73728 B
    cudaFuncSetAttribute(attn_kernel,
                         cudaFuncAttributeMaxDynamicSharedMemorySize, smem);
    dim3 grid(S_ / 128, B_ * H_);
    attn_kernel<<<grid, 256, smem>>>(Q, K, V, SC, O);
}

// round 10
// speedup vs baseline: 1.0025x; 1.0025x over previous
#include <cuda_runtime.h>
#include <cstdint>

#define B_ 4
#define H_ 16
#define S_ 1024
#define D_ 64

#define KEEP_THRESH 0xE6666600u   // bits < thresh  <=>  uniform < 0.9f (verified)

// ---------------------------------------------------------------------------
// add via IMAD so it lands on the fma pipe (threefry is otherwise alu-bound)
// ---------------------------------------------------------------------------
__device__ __forceinline__ uint32_t addm(uint32_t a, uint32_t b) {
    uint32_t r;
    asm("mad.lo.u32 %0, %1, 1, %2;" : "=r"(r) : "r"(a), "r"(b));
    return r;
}

// ---------------------------------------------------------------------------
// Threefry-2x32 specialized for key (0,42): keep bit for counter (0,c).
// Bit-exact vs JAX partitionable path (verified rel_err 6.4e-8 / 4.1e-5).
// ---------------------------------------------------------------------------
__device__ __forceinline__ uint32_t tf_keep(uint32_t ctr) {
    const uint32_t KS2 = 0x1BD11BDAu ^ 42u;
    uint32_t x0 = 0u, x1 = ctr + 42u;
#define TF_R(r) { x0 = addm(x0, x1); x1 = __funnelshift_l(x1, x1, (r)); x1 ^= x0; }
    TF_R(13) TF_R(15) TF_R(26) TF_R(6)
    x0 = addm(x0, 42u);  x1 = addm(x1, KS2 + 1u);
    TF_R(17) TF_R(29) TF_R(16) TF_R(24)
    x0 = addm(x0, KS2);  x1 = addm(x1, 2u);
    TF_R(13) TF_R(15) TF_R(26) TF_R(6)
    /* x0 += 0 */        x1 = addm(x1, 45u);
    TF_R(17) TF_R(29) TF_R(16) TF_R(24)
    x0 = addm(x0, 42u);  x1 = addm(x1, KS2 + 4u);
    TF_R(13) TF_R(15) TF_R(26) TF_R(6)
    x0 = addm(x0, KS2);  x1 = addm(x1, 5u);
#undef TF_R
    return ((x0 ^ x1) < KEEP_THRESH) ? 1u : 0u;
}

// ---------------------------------------------------------------------------
// bf16 helpers
// ---------------------------------------------------------------------------
__device__ __forceinline__ uint32_t pack2(float lo, float hi) {
    uint32_t r;
    asm("cvt.rn.bf16x2.f32 %0, %1, %2;" : "=r"(r) : "f"(hi), "f"(lo));
    return r;
}
__device__ __forceinline__ float blo(uint32_t w) { return __uint_as_float(w << 16); }
__device__ __forceinline__ float bhi(uint32_t w) { return __uint_as_float(w & 0xffff0000u); }
__device__ __forceinline__ void split2(float a, float b, uint32_t& h, uint32_t& l) {
    h = pack2(a, b);
    l = pack2(a - blo(h), b - bhi(h));
}

// d += A(bf16) * B(bf16), m16n8k16
__device__ __forceinline__ void mma16(float d[4], const uint32_t a[4],
                                      uint32_t b0, uint32_t b1) {
    asm volatile(
        "mma.sync.aligned.m16n8k16.row.col.f32.bf16.bf16.f32 "
        "{%0,%1,%2,%3}, {%4,%5,%6,%7}, {%8,%9}, {%0,%1,%2,%3};"
        : "+f"(d[0]), "+f"(d[1]), "+f"(d[2]), "+f"(d[3])
        : "r"(a[0]), "r"(a[1]), "r"(a[2]), "r"(a[3]), "r"(b0), "r"(b1));
}

__device__ __forceinline__ void ldm_x4(uint32_t r[4], uint32_t addr) {
    asm volatile("ldmatrix.sync.aligned.m8n8.x4.shared.b16 {%0,%1,%2,%3}, [%4];"
                 : "=r"(r[0]), "=r"(r[1]), "=r"(r[2]), "=r"(r[3]) : "r"(addr));
}

__device__ __forceinline__ void cp16(uint32_t saddr, const float* g) {
    asm volatile("cp.async.cg.shared.global [%0], [%1], 16;"
                 :: "r"(saddr), "l"(g));
}

#define PW 36   // bf16x2 word stride: 144 B/row
#define ST 68   // fp32 staging word stride: 272 B/row

// word offsets (P lives in registers; staging holds next tile's raw fp32 K/V)
#define W_QH 0
#define W_QL (128 * PW)
#define W_KH (2 * 128 * PW)
#define W_KL (W_KH + 64 * PW)
#define W_VH (W_KL + 64 * PW)
#define W_VL (W_VH + 64 * PW)
#define W_SK (W_VL + 64 * PW)            // 18432
#define W_SV (W_SK + 64 * ST)            // +4352
#define W_TOT (W_SV + 64 * ST)           // 27136 words = 108544 B -> 2 CTAs/SM

// ---------------------------------------------------------------------------
__global__ void __launch_bounds__(256, 2)
attn_kernel(const float* __restrict__ Q, const float* __restrict__ K,
            const float* __restrict__ V, const uint32_t* __restrict__ scale_ptr,
            float* __restrict__ O) {
    extern __shared__ uint32_t smw[];

    const int tid  = threadIdx.x;
    const int warp = tid >> 5;           // 0..7, owns rows [16w, 16w+16)
    const int lane = tid & 31;
    const int gid  = lane >> 2;          // 0..7
    const int tig  = lane & 3;           // 0..3
    const int bh   = blockIdx.y;
    const int qb   = blockIdx.x << 7;
    const int r0   = warp * 16 + gid;

    uint32_t sw = *scale_ptr;
    float scale = (sw & 0x7f800000u) ? __uint_as_float(sw) : (float)(int)sw;

    // per-lane ldmatrix base addresses (byte, shared space)
    const uint32_t sb = (uint32_t)__cvta_generic_to_shared(smw);
    const uint32_t laneA = (uint32_t)((lane & 15) * PW + ((lane & 16) ? 4 : 0));
    const uint32_t laneBK = (uint32_t)(((lane < 16) ? W_KH : W_KL)
                                       + (lane & 7) * PW + ((lane & 8) ? 4 : 0));
    const uint32_t laneBV = (uint32_t)(((lane < 16) ? W_VH : W_VL)
                                       + (lane & 7) * PW + ((lane & 8) ? 4 : 0));
    const uint32_t aQH = sb + 4u * (W_QH + (uint32_t)(warp * 16) * PW + laneA);
    const uint32_t aQL = sb + 4u * (W_QL + (uint32_t)(warp * 16) * PW + laneA);
    const uint32_t aK  = sb + 4u * laneBK;
    const uint32_t aV  = sb + 4u * laneBV;

    // global bit-index base for this lane's dropout rows (row r0 and r0+8)
    const uint32_t bit_base =
        ((uint32_t)(bh * S_ + qb + r0) << 10) + 2u * (uint32_t)tig;

    const float* Kbh = K + (size_t)bh * S_ * D_;
    const float* Vbh = V + (size_t)bh * S_ * D_;

    // cp.async lane assignment: 4 segs/thread per tensor
    const int cpr = tid >> 1;                    // row pairs... (see below)

    // ---- prefetch tile 0 K/V (raw fp32) into staging ----
#pragma unroll
    for (int i = 0; i < 4; i++) {
        int lin = tid + (i << 8);                // 0..1023
        int r = lin >> 4, sg = (lin & 15) << 2;  // row, float-offset
        cp16(sb + 4u * (uint32_t)(W_SK + r * ST + sg), Kbh + r * 64 + sg);
        cp16(sb + 4u * (uint32_t)(W_SV + r * ST + sg), Vbh + r * 64 + sg);
    }
    asm volatile("cp.async.commit_group;" ::: "memory");
    (void)cpr;

    // ---- Q prologue: stage scaled hi/lo bf16x2 words into smem ----
    {
        int r = tid >> 1, half = (tid & 1) * 32;
        const float4* Qp = reinterpret_cast<const float4*>(
            Q + ((size_t)bh * S_ + qb + r) * D_ + half);
        int wb = r * PW + (half >> 1);
#pragma unroll
        for (int i = 0; i < 8; i++) {
            float4 v = Qp[i];
            uint32_t h0, l0, h1, l1;
            split2(v.x * scale, v.y * scale, h0, l0);
            split2(v.z * scale, v.w * scale, h1, l1);
            smw[W_QH + wb + 2 * i]     = h0;
            smw[W_QH + wb + 2 * i + 1] = h1;
            smw[W_QL + wb + 2 * i]     = l0;
            smw[W_QL + wb + 2 * i + 1] = l1;
        }
    }

    float m_[2], l_[2];
    float o[8][4];
    m_[0] = m_[1] = -1e30f;
    l_[0] = l_[1] = 0.f;
#pragma unroll
    for (int n = 0; n < 8; n++)
#pragma unroll
        for (int c = 0; c < 4; c++) o[n][c] = 0.f;

#pragma unroll 1
    for (int t = 0; t < 16; t++) {
        asm volatile("cp.async.wait_group 0;" ::: "memory");
        __syncthreads();                 // staging ready; prev readers done

        // ---- K split: staging fp32 -> bf16 hi/lo (LDS, no LDG stall) ----
        {
            int r = tid >> 2, qv = (tid & 3) << 4;
            const float4* Kst = reinterpret_cast<const float4*>(
                reinterpret_cast<const float*>(smw) + W_SK + r * ST + qv);
            uint32_t kh[8], kl[8];
#pragma unroll
            for (int i = 0; i < 4; i++) {
                float4 v = Kst[i];
                split2(v.x, v.y, kh[2 * i],     kl[2 * i]);
                split2(v.z, v.w, kh[2 * i + 1], kl[2 * i + 1]);
            }
            int wb = r * PW + (qv >> 1);
            *reinterpret_cast<uint4*>(smw + W_KH + wb) =
                make_uint4(kh[0], kh[1], kh[2], kh[3]);
            *reinterpret_cast<uint4*>(smw + W_KH + wb + 4) =
                make_uint4(kh[4], kh[5], kh[6], kh[7]);
            *reinterpret_cast<uint4*>(smw + W_KL + wb) =
                make_uint4(kl[0], kl[1], kl[2], kl[3]);
            *reinterpret_cast<uint4*>(smw + W_KL + wb + 4) =
                make_uint4(kl[4], kl[5], kl[6], kl[7]);
        }

        // ---- V split: staging fp32 -> transposed bf16 hi/lo ----
        {
            int kp = tid & 31, db = (tid >> 5) << 3;
            const float* s0 = reinterpret_cast<const float*>(smw)
                              + W_SV + (2 * kp) * ST + db;
            float4 a0 = reinterpret_cast<const float4*>(s0)[0];
            float4 a1 = reinterpret_cast<const float4*>(s0)[1];
            float4 b0 = reinterpret_cast<const float4*>(s0 + ST)[0];
            float4 b1 = reinterpret_cast<const float4*>(s0 + ST)[1];
            float fa[8] = {a0.x, a0.y, a0.z, a0.w, a1.x, a1.y, a1.z, a1.w};
            float fb[8] = {b0.x, b0.y, b0.z, b0.w, b1.x, b1.y, b1.z, b1.w};
#pragma unroll
            for (int i = 0; i < 8; i++) {
                uint32_t h, l;
                split2(fa[i], fb[i], h, l);    // lo=key 2kp, hi=key 2kp+1
                smw[W_VH + (db + i) * PW + kp] = h;
                smw[W_VL + (db + i) * PW + kp] = l;
            }
        }
        __syncthreads();                 // bf16 tiles ready; staging free

        // ---- prefetch tile t+1 into staging (overlaps QK/threefry/PV) ----
        if (t < 15) {
            const float* Kt = Kbh + (t + 1) * 64 * D_;
            const float* Vt = Vbh + (t + 1) * 64 * D_;
#pragma unroll
            for (int i = 0; i < 4; i++) {
                int lin = tid + (i << 8);
                int r = lin >> 4, sg = (lin & 15) << 2;
                cp16(sb + 4u * (uint32_t)(W_SK + r * ST + sg), Kt + r * 64 + sg);
                cp16(sb + 4u * (uint32_t)(W_SV + r * ST + sg), Vt + r * 64 + sg);
            }
        }
        asm volatile("cp.async.commit_group;" ::: "memory");

        // ---- QK: 3-term bf16, Q via ldmatrix, K via ldmatrix.x4 ----
        float s[8][4];
#pragma unroll
        for (int n = 0; n < 8; n++)
#pragma unroll
            for (int c = 0; c < 4; c++) s[n][c] = 0.f;

#pragma unroll
        for (int ks = 0; ks < 4; ks++) {
            uint32_t qh[4], ql[4];
            ldm_x4(qh, aQH + ks * 32u);
            ldm_x4(ql, aQL + ks * 32u);
#pragma unroll
            for (int n = 0; n < 8; n++) {
                uint32_t kb[4];
                ldm_x4(kb, aK + 4u * (uint32_t)(n * 8 * PW + ks * 8));
                mma16(s[n], qh, kb[0], kb[1]);
                mma16(s[n], ql, kb[0], kb[1]);
                mma16(s[n], qh, kb[2], kb[3]);
            }
        }

        // ---- fused dropout mask: 32 threefry evals (fills HMMA latency) ----
        uint32_t lm0 = 0u, lm1 = 0u;
        {
            uint32_t c0 = bit_base + (uint32_t)(t * 64);
            uint32_t c1 = c0 + (8u << 10);
#pragma unroll 1
            for (int j = 0; j < 8; j++) {
                uint32_t cj0 = c0 + 8u * (uint32_t)j;
                uint32_t cj1 = c1 + 8u * (uint32_t)j;
                lm0 |= tf_keep(cj0)      << (2 * j);
                lm0 |= tf_keep(cj0 + 1u) << (2 * j + 1);
                lm1 |= tf_keep(cj1)      << (2 * j);
                lm1 |= tf_keep(cj1 + 1u) << (2 * j + 1);
            }
        }

        // ---- online softmax (row lives on a lane quad) ----
#pragma unroll
        for (int h = 0; h < 2; h++) {
            float mx = -1e30f;
#pragma unroll
            for (int n = 0; n < 8; n++)
                mx = fmaxf(mx, fmaxf(s[n][2 * h], s[n][2 * h + 1]));
            mx = fmaxf(mx, __shfl_xor_sync(0xffffffffu, mx, 1));
            mx = fmaxf(mx, __shfl_xor_sync(0xffffffffu, mx, 2));
            float mnew = fmaxf(m_[h], mx);
            float corr = __expf(m_[h] - mnew);
            m_[h] = mnew;
            float sum = 0.f;
#pragma unroll
            for (int n = 0; n < 8; n++) {
                float e0 = __expf(s[n][2 * h] - mnew);
                float e1 = __expf(s[n][2 * h + 1] - mnew);
                s[n][2 * h] = e0;
                s[n][2 * h + 1] = e1;
                sum += e0 + e1;
            }
            sum += __shfl_xor_sync(0xffffffffu, sum, 1);
            sum += __shfl_xor_sync(0xffffffffu, sum, 2);
            l_[h] = l_[h] * corr + sum;
#pragma unroll
            for (int n = 0; n < 8; n++) {
                o[n][2 * h] *= corr;
                o[n][2 * h + 1] *= corr;
            }
        }

        // ---- PV: dropout + pack P chunk in regs, V via ldmatrix.x4 ----
#pragma unroll
        for (int ks = 0; ks < 4; ks++) {
            uint32_t aph[4], apl[4];
#pragma unroll
            for (int q = 0; q < 4; q++) {          // q = 2*(n-2ks) + h
                int n = 2 * ks + (q >> 1);
                int h = q & 1;
                uint32_t lm = h ? lm1 : lm0;
                float p0 = ((lm >> (2 * n)) & 1u)     ? s[n][2 * h] : 0.f;
                float p1 = ((lm >> (2 * n + 1)) & 1u) ? s[n][2 * h + 1] : 0.f;
                int ar = (q >> 1) * 2 + h;         // n-low: a0/a1, n-high: a2/a3
                split2(p0, p1, aph[ar], apl[ar]);
            }
#pragma unroll
            for (int n = 0; n < 8; n++) {
                uint32_t vb[4];
                ldm_x4(vb, aV + 4u * (uint32_t)(n * 8 * PW + ks * 8));
                mma16(o[n], aph, vb[0], vb[1]);
                mma16(o[n], aph, vb[2], vb[3]);
                mma16(o[n], apl, vb[0], vb[1]);
            }
        }
    }

    // ---- epilogue: O / (0.9 * l), write global ----
#pragma unroll
    for (int h = 0; h < 2; h++) {
        float inv = 1.f / (0.9f * l_[h]);
        int row = qb + r0 + h * 8;
        float* Op = O + ((size_t)bh * S_ + row) * D_;
#pragma unroll
        for (int n = 0; n < 8; n++) {
            float2 v;
            v.x = o[n][2 * h] * inv;
            v.y = o[n][2 * h + 1] * inv;
            *reinterpret_cast<float2*>(Op + n * 8 + 2 * tig) = v;
        }
    }
}

// ---------------------------------------------------------------------------
extern "C" void kernel_launch(void* const* d_in, const int* in_sizes, int n_in,
                              void* d_out, int out_size) {
    (void)in_sizes; (void)n_in; (void)out_size;
    const float*    Q  = (const float*)d_in[0];
    const float*    K  = (const float*)d_in[1];
    const float*    V  = (const float*)d_in[2];
    const uint32_t* SC = (const uint32_t*)d_in[3];
    float*          O  = (float*)d_out;

    const int smem = W_TOT * (int)sizeof(uint32_t);   // 108544 B
    cudaFuncSetAttribute(attn_kernel,
                         cudaFuncAttributeMaxDynamicSharedMemorySize, smem);
    dim3 grid(S_ / 128, B_ * H_);
    attn_kernel<<<grid, 256, smem>>>(Q, K, V, SC, O);
}